// round 1
// baseline (speedup 1.0000x reference)
#include <cuda_runtime.h>
#include <cuda_bf16.h>

// ----------------------------------------------------------------------------
// Linear_14912126452257:
//   new_W = W + scatter_add(shira_indices, shira_weight)   [4096 x 4096]
//   out   = x @ new_W^T + bias                              x: [8192, 4096]
//
// Phase 1: copy W into a __device__ scratch (64MB), scatter-add deltas (atomics,
//          duplicate indices possible).
// Phase 2: SIMT fp32 GEMM, 128x128 block tile, BK=16, 8x8 per-thread register
//          tile, gmem->register prefetch to hide DRAM latency.
// ----------------------------------------------------------------------------

#define BM 128
#define BN 128
#define BK 16

// 64 MB scratch for the modified weight (allocation-free per harness rules).
__device__ float g_W[4096u * 4096u];

// ---------------- Phase 1 kernels ----------------

__global__ void prep_copy_kernel(const float* __restrict__ w, int n4) {
    float4* dst = reinterpret_cast<float4*>(g_W);
    const float4* src = reinterpret_cast<const float4*>(w);
    for (int i = blockIdx.x * blockDim.x + threadIdx.x; i < n4;
         i += gridDim.x * blockDim.x) {
        dst[i] = src[i];
    }
}

__global__ void prep_scatter_kernel(const float* __restrict__ sw,
                                    const int* __restrict__ rows,
                                    const int* __restrict__ cols,
                                    int nnz, int K) {
    int i = blockIdx.x * blockDim.x + threadIdx.x;
    if (i < nnz) {
        atomicAdd(&g_W[(long long)rows[i] * K + cols[i]], sw[i]);
    }
}

// ---------------- Phase 2: GEMM ----------------
// C[m][n] = sum_k A[m][k] * Wn[n][k] + bias[n]
// Both operands are K-contiguous (NT GEMM).

__global__ __launch_bounds__(256, 2)
void gemm_kernel(const float* __restrict__ A,
                 const float* __restrict__ bias,
                 float* __restrict__ C,
                 int M, int N, int K) {
    __shared__ float As[BK][BM + 4];   // [k][m], +4 keeps float4 alignment
    __shared__ float Bs[BK][BN + 4];   // [k][n]

    const float* __restrict__ B = g_W;

    const int tid = threadIdx.x;
    const int m0 = blockIdx.y * BM;
    const int n0 = blockIdx.x * BN;

    // Warp layout: 8 warps as 2 (m) x 4 (n); warp tile 64x32.
    // Lane layout: 8 (m) x 4 (n); thread tile 8x8 (contiguous rows/cols).
    const int warp = tid >> 5;
    const int lane = tid & 31;
    const int warp_m = warp & 1;
    const int warp_n = warp >> 1;
    const int tm = lane & 7;
    const int tn = lane >> 3;
    const int a_off = warp_m * 64 + tm * 8;   // row offset within block tile
    const int b_off = warp_n * 32 + tn * 8;   // col offset within block tile

    // Gmem load mapping: 256 threads, each loads 2 rows of 1 float4 per array.
    const int lrow = tid >> 2;   // 0..63
    const int lc4  = tid & 3;    // 0..3  (float4 column within BK=16)

    const float* Abase = A + (long long)(m0 + lrow) * K + lc4 * 4;
    const float* Bbase = B + (long long)(n0 + lrow) * K + lc4 * 4;
    const long long arow_stride = 64LL * K;

    float acc[8][8] = {};
    float4 pa[2], pb[2];

    const int ntiles = K / BK;

    // Prologue: prefetch tile 0
    {
        const float* pA = Abase;
        const float* pB = Bbase;
        pa[0] = *(const float4*)(pA);
        pa[1] = *(const float4*)(pA + arow_stride);
        pb[0] = *(const float4*)(pB);
        pb[1] = *(const float4*)(pB + arow_stride);
    }

    for (int kt = 0; kt < ntiles; kt++) {
        __syncthreads();   // previous compute must finish before overwrite

        // Store prefetched tile to smem (transposed to [k][m])
        #pragma unroll
        for (int h = 0; h < 2; h++) {
            int r = lrow + h * 64;
            As[lc4 * 4 + 0][r] = (h ? pa[1].x : pa[0].x);
            As[lc4 * 4 + 1][r] = (h ? pa[1].y : pa[0].y);
            As[lc4 * 4 + 2][r] = (h ? pa[1].z : pa[0].z);
            As[lc4 * 4 + 3][r] = (h ? pa[1].w : pa[0].w);
            Bs[lc4 * 4 + 0][r] = (h ? pb[1].x : pb[0].x);
            Bs[lc4 * 4 + 1][r] = (h ? pb[1].y : pb[0].y);
            Bs[lc4 * 4 + 2][r] = (h ? pb[1].z : pb[0].z);
            Bs[lc4 * 4 + 3][r] = (h ? pb[1].w : pb[0].w);
        }
        __syncthreads();

        // Prefetch next tile into registers (hides DRAM latency under compute)
        if (kt + 1 < ntiles) {
            const float* pA = Abase + (kt + 1) * BK;
            const float* pB = Bbase + (kt + 1) * BK;
            pa[0] = *(const float4*)(pA);
            pa[1] = *(const float4*)(pA + arow_stride);
            pb[0] = *(const float4*)(pB);
            pb[1] = *(const float4*)(pB + arow_stride);
        }

        // Compute on current smem tiles
        #pragma unroll
        for (int k = 0; k < BK; k++) {
            float af[8], bf[8];
            *(float4*)&af[0] = *(const float4*)&As[k][a_off];
            *(float4*)&af[4] = *(const float4*)&As[k][a_off + 4];
            *(float4*)&bf[0] = *(const float4*)&Bs[k][b_off];
            *(float4*)&bf[4] = *(const float4*)&Bs[k][b_off + 4];
            #pragma unroll
            for (int i = 0; i < 8; i++) {
                #pragma unroll
                for (int j = 0; j < 8; j++) {
                    acc[i][j] = fmaf(af[i], bf[j], acc[i][j]);
                }
            }
        }
    }

    // Epilogue: add bias, vectorized stores
    float bv[8];
    #pragma unroll
    for (int j = 0; j < 8; j++) bv[j] = bias[n0 + b_off + j];

    #pragma unroll
    for (int i = 0; i < 8; i++) {
        int row = m0 + a_off + i;
        float* cp = C + (long long)row * N + n0 + b_off;
        float4 v0, v1;
        v0.x = acc[i][0] + bv[0];
        v0.y = acc[i][1] + bv[1];
        v0.z = acc[i][2] + bv[2];
        v0.w = acc[i][3] + bv[3];
        v1.x = acc[i][4] + bv[4];
        v1.y = acc[i][5] + bv[5];
        v1.z = acc[i][6] + bv[6];
        v1.w = acc[i][7] + bv[7];
        *(float4*)(cp)     = v0;
        *(float4*)(cp + 4) = v1;
    }
}

// ---------------- launch ----------------

extern "C" void kernel_launch(void* const* d_in, const int* in_sizes, int n_in,
                              void* d_out, int out_size) {
    const float* x    = (const float*)d_in[0];   // [4,2048,4096] -> [8192,4096]
    const float* w    = (const float*)d_in[1];   // [4096,4096]
    const float* bias = (const float*)d_in[2];   // [4096]
    const float* sw   = (const float*)d_in[3];   // [nnz]
    const int*   idx  = (const int*)d_in[4];     // [2, nnz]
    float* out = (float*)d_out;

    const int N = in_sizes[2];           // 4096 (out_features)
    const int K = in_sizes[1] / N;       // 4096 (in_features)
    const int M = in_sizes[0] / K;       // 8192
    const int nnz = in_sizes[3];         // 262144

    // Phase 1: new_W = W + scatter(delta)
    const int n4 = (N * K) / 4;
    prep_copy_kernel<<<1024, 256>>>(w, n4);
    prep_scatter_kernel<<<(nnz + 255) / 256, 256>>>(sw, idx, idx + nnz, nnz, K);

    // Phase 2: GEMM + bias
    dim3 grid(N / BN, M / BM);   // (32, 64)
    gemm_kernel<<<grid, 256>>>(x, bias, out, M, N, K);
}

// round 3
// speedup vs baseline: 2.2188x; 2.2188x over previous
#include <cuda_runtime.h>
#include <cuda_bf16.h>
#include <cstdint>

// ----------------------------------------------------------------------------
// Round 3: mma.sync bf16 GEMM with bf16x3 compensation (tcgen05 unavailable:
// harness compiles for compute_103, no "a" features).
//
//   Wf = W + scatter(delta)                (fp32, g_Wf)
//   A  = [bf16hi(x) | bf16hi(x) | bf16lo(x)]    [8192, 12288] bf16
//   B  = [bf16hi(Wf)| bf16lo(Wf)| bf16hi(Wf)]   [4096, 12288] bf16
//   out = A @ B^T + bias   (fp32 accum)  == hi*whi + hi*wlo + lo*whi
//
// GEMM: 128x128 CTA tile, BK=32, 4-stage cp.async pipeline, ldmatrix + HMMA.
// ----------------------------------------------------------------------------

#define BM 128
#define BN 128
#define BK 32
#define STAGES 4
#define K3 12288
#define ROW_STRIDE 80                       // 64B data + 16B pad: (5r+c)%8 conflict-free
#define A_STAGE_BYTES (BM * ROW_STRIDE)     // 10240
#define B_STAGE_BYTES (BN * ROW_STRIDE)     // 10240
#define STAGE_BYTES (A_STAGE_BYTES + B_STAGE_BYTES)
#define SMEM_TOTAL (STAGES * STAGE_BYTES)   // 81920

__device__ float          g_Wf[4096u * 4096u];          // 64 MB
__device__ __nv_bfloat16  g_A[8192u * 12288u];          // 192 MB
__device__ __nv_bfloat16  g_B[4096u * 12288u];          // 96 MB

// ---------------- helpers ----------------

__device__ __forceinline__ uint32_t smem_u32(const void* p) {
    uint32_t a;
    asm("{ .reg .u64 t; cvta.to.shared.u64 t, %1; cvt.u32.u64 %0, t; }"
        : "=r"(a) : "l"(p));
    return a;
}

__device__ __forceinline__ void cp_async16(uint32_t dst, const void* src) {
    asm volatile("cp.async.cg.shared.global [%0], [%1], 16;"
                 :: "r"(dst), "l"(src) : "memory");
}
#define CP_COMMIT() asm volatile("cp.async.commit_group;" ::: "memory")
#define CP_WAIT(n)  asm volatile("cp.async.wait_group %0;" :: "n"(n) : "memory")

__device__ __forceinline__ void ldmatrix4(uint32_t* r, uint32_t addr) {
    asm volatile("ldmatrix.sync.aligned.m8n8.x4.shared.b16 {%0,%1,%2,%3}, [%4];"
                 : "=r"(r[0]), "=r"(r[1]), "=r"(r[2]), "=r"(r[3]) : "r"(addr));
}

__device__ __forceinline__ void mma16816(float* d, const uint32_t* a,
                                         const uint32_t* b) {
    asm volatile(
        "mma.sync.aligned.m16n8k16.row.col.f32.bf16.bf16.f32 "
        "{%0,%1,%2,%3}, {%4,%5,%6,%7}, {%8,%9}, {%0,%1,%2,%3};"
        : "+f"(d[0]), "+f"(d[1]), "+f"(d[2]), "+f"(d[3])
        : "r"(a[0]), "r"(a[1]), "r"(a[2]), "r"(a[3]), "r"(b[0]), "r"(b[1]));
}

// ---------------- Phase 1: prep kernels ----------------

__global__ void prep_wcopy_kernel(const float* __restrict__ w, int n4) {
    float4* dst = reinterpret_cast<float4*>(g_Wf);
    const float4* src = reinterpret_cast<const float4*>(w);
    for (int i = blockIdx.x * blockDim.x + threadIdx.x; i < n4;
         i += gridDim.x * blockDim.x)
        dst[i] = src[i];
}

__global__ void prep_scatter_kernel(const float* __restrict__ sw,
                                    const int* __restrict__ rows,
                                    const int* __restrict__ cols,
                                    int nnz, int K) {
    int i = blockIdx.x * blockDim.x + threadIdx.x;
    if (i < nnz)
        atomicAdd(&g_Wf[(size_t)rows[i] * K + cols[i]], sw[i]);
}

__device__ __forceinline__ void split2(float x, float y,
                                       __nv_bfloat162& hi, __nv_bfloat162& lo) {
    __nv_bfloat16 hx = __float2bfloat16_rn(x);
    __nv_bfloat16 hy = __float2bfloat16_rn(y);
    __nv_bfloat16 lx = __float2bfloat16_rn(x - __bfloat162float(hx));
    __nv_bfloat16 ly = __float2bfloat16_rn(y - __bfloat162float(hy));
    hi = __nv_bfloat162(hx, hy);
    lo = __nv_bfloat162(lx, ly);
}

// B row n: [ whi | wlo | whi ]
__global__ void prep_wsplit_kernel(int n4, int K) {
    const float4* src = reinterpret_cast<const float4*>(g_Wf);
    const int rowq = K / 4;
    for (int i = blockIdx.x * blockDim.x + threadIdx.x; i < n4;
         i += gridDim.x * blockDim.x) {
        float4 v = src[i];
        int row = i / rowq, col = (i % rowq) * 4;
        __nv_bfloat162 h0, l0, h1, l1;
        split2(v.x, v.y, h0, l0);
        split2(v.z, v.w, h1, l1);
        size_t base = (size_t)row * K3 + col;
        __nv_bfloat162* p0 = reinterpret_cast<__nv_bfloat162*>(&g_B[base]);
        __nv_bfloat162* p1 = reinterpret_cast<__nv_bfloat162*>(&g_B[base + K]);
        __nv_bfloat162* p2 = reinterpret_cast<__nv_bfloat162*>(&g_B[base + 2 * K]);
        p0[0] = h0; p0[1] = h1;
        p1[0] = l0; p1[1] = l1;
        p2[0] = h0; p2[1] = h1;
    }
}

// A row m: [ xhi | xhi | xlo ]
__global__ void prep_xsplit_kernel(const float* __restrict__ x, int n4, int K) {
    const float4* src = reinterpret_cast<const float4*>(x);
    const int rowq = K / 4;
    for (int i = blockIdx.x * blockDim.x + threadIdx.x; i < n4;
         i += gridDim.x * blockDim.x) {
        float4 v = src[i];
        int row = i / rowq, col = (i % rowq) * 4;
        __nv_bfloat162 h0, l0, h1, l1;
        split2(v.x, v.y, h0, l0);
        split2(v.z, v.w, h1, l1);
        size_t base = (size_t)row * K3 + col;
        __nv_bfloat162* p0 = reinterpret_cast<__nv_bfloat162*>(&g_A[base]);
        __nv_bfloat162* p1 = reinterpret_cast<__nv_bfloat162*>(&g_A[base + K]);
        __nv_bfloat162* p2 = reinterpret_cast<__nv_bfloat162*>(&g_A[base + 2 * K]);
        p0[0] = h0; p0[1] = h1;
        p1[0] = h0; p1[1] = h1;
        p2[0] = l0; p2[1] = l1;
    }
}

// ---------------- Phase 2: GEMM ----------------

__device__ __forceinline__ void load_stage(uint32_t stage_base, int tid,
                                           const __nv_bfloat16* gA,
                                           const __nv_bfloat16* gB, int k0) {
    // A: 128 rows x 4 chunks (16B) = 512; B same.
    #pragma unroll
    for (int i = 0; i < 2; i++) {
        int u = i * 256 + tid;
        int row = u >> 2, ch = u & 3;
        cp_async16(stage_base + row * ROW_STRIDE + ch * 16,
                   gA + (size_t)row * K3 + k0 + ch * 8);
    }
    #pragma unroll
    for (int i = 0; i < 2; i++) {
        int u = i * 256 + tid;
        int row = u >> 2, ch = u & 3;
        cp_async16(stage_base + A_STAGE_BYTES + row * ROW_STRIDE + ch * 16,
                   gB + (size_t)row * K3 + k0 + ch * 8);
    }
}

__global__ __launch_bounds__(256, 2)
void gemm_kernel(const float* __restrict__ bias, float* __restrict__ C, int N) {
    extern __shared__ char smem[];
    const uint32_t sbase = smem_u32(smem);

    const int tid = threadIdx.x;
    const int warp = tid >> 5;
    const int lane = tid & 31;
    const int warp_m = warp & 1;     // 2 x 4 warp grid
    const int warp_n = warp >> 1;

    const int m0 = blockIdx.y * BM;
    const int n0 = blockIdx.x * BN;

    const __nv_bfloat16* gA = g_A + (size_t)m0 * K3;
    const __nv_bfloat16* gB = g_B + (size_t)n0 * K3;

    // ldmatrix per-lane addressing
    const int a_row = warp_m * 64 + (lane & 15);        // + mi*16
    const int a_chb = lane >> 4;                        // 0/1 -> k half
    const int b_row = warp_n * 32 + ((lane >> 4) << 3) + (lane & 7);  // + bi*16
    const int b_ch  = (lane >> 3) & 1;

    float acc[4][4][4] = {};

    // Prologue: stages 0..STAGES-2
    #pragma unroll
    for (int s = 0; s < STAGES - 1; s++) {
        load_stage(sbase + s * STAGE_BYTES, tid, gA, gB, s * BK);
        CP_COMMIT();
    }

    const int NT = K3 / BK;   // 384
    for (int kt = 0; kt < NT; kt++) {
        CP_WAIT(STAGES - 2);
        __syncthreads();

        // Issue next stage's loads (buffer (kt-1)%STAGES, safe after barrier)
        const int pf = kt + STAGES - 1;
        if (pf < NT)
            load_stage(sbase + (pf % STAGES) * STAGE_BYTES, tid, gA, gB, pf * BK);
        CP_COMMIT();

        const uint32_t As = sbase + (kt % STAGES) * STAGE_BYTES;
        const uint32_t Bs = As + A_STAGE_BYTES;

        #pragma unroll
        for (int ks = 0; ks < 2; ks++) {
            uint32_t af[4][4], bf[2][4];
            #pragma unroll
            for (int mi = 0; mi < 4; mi++)
                ldmatrix4(af[mi], As + (a_row + mi * 16) * ROW_STRIDE
                                     + (ks * 2 + a_chb) * 16);
            #pragma unroll
            for (int bi = 0; bi < 2; bi++)
                ldmatrix4(bf[bi], Bs + (b_row + bi * 16) * ROW_STRIDE
                                     + (ks * 2 + b_ch) * 16);
            #pragma unroll
            for (int mi = 0; mi < 4; mi++) {
                #pragma unroll
                for (int ni = 0; ni < 4; ni++)
                    mma16816(acc[mi][ni], af[mi], &bf[ni >> 1][(ni & 1) * 2]);
            }
        }
    }

    // Epilogue
    const int l4 = lane >> 2;
    const int l2 = (lane & 3) * 2;
    #pragma unroll
    for (int ni = 0; ni < 4; ni++) {
        const int col = n0 + warp_n * 32 + ni * 8 + l2;
        const float2 bv = *reinterpret_cast<const float2*>(&bias[col]);
        #pragma unroll
        for (int mi = 0; mi < 4; mi++) {
            const int row = m0 + warp_m * 64 + mi * 16 + l4;
            float2 v0, v1;
            v0.x = acc[mi][ni][0] + bv.x;
            v0.y = acc[mi][ni][1] + bv.y;
            v1.x = acc[mi][ni][2] + bv.x;
            v1.y = acc[mi][ni][3] + bv.y;
            *reinterpret_cast<float2*>(&C[(size_t)row * N + col]) = v0;
            *reinterpret_cast<float2*>(&C[(size_t)(row + 8) * N + col]) = v1;
        }
    }
}

// ---------------- launch ----------------

extern "C" void kernel_launch(void* const* d_in, const int* in_sizes, int n_in,
                              void* d_out, int out_size) {
    const float* x    = (const float*)d_in[0];
    const float* w    = (const float*)d_in[1];
    const float* bias = (const float*)d_in[2];
    const float* sw   = (const float*)d_in[3];
    const int*   idx  = (const int*)d_in[4];
    float* out = (float*)d_out;

    const int N = in_sizes[2];        // 4096
    const int K = in_sizes[1] / N;    // 4096
    const int M = in_sizes[0] / K;    // 8192
    const int nnz = in_sizes[3];      // 262144

    static bool attr_done = false;
    if (!attr_done) {
        cudaFuncSetAttribute(gemm_kernel,
                             cudaFuncAttributeMaxDynamicSharedMemorySize, SMEM_TOTAL);
        attr_done = true;
    }

    prep_wcopy_kernel<<<1024, 256>>>(w, (N * K) / 4);
    prep_scatter_kernel<<<(nnz + 255) / 256, 256>>>(sw, idx, idx + nnz, nnz, K);
    prep_wsplit_kernel<<<1024, 256>>>((N * K) / 4, K);
    prep_xsplit_kernel<<<2048, 256>>>(x, (M / 4) * K, K);

    dim3 grid(N / BN, M / BM);   // (32, 64)
    gemm_kernel<<<grid, 256, SMEM_TOTAL>>>(bias, out, N);
}